// round 13
// baseline (speedup 1.0000x reference)
#include <cuda_runtime.h>
#include <cuda_fp16.h>
#include <math.h>

#define B_   4096
#define N_   32
#define D_   256
#define NT   4
#define NH   8
#define TOK  131072
#define WSZ  65536
#define BPAD 40

// ---------------- scratch (static device allocations) ----------------
__device__ __half g_W16[(size_t)3 * NT * WSZ];          // W^T: [mat][e][n][k] fp16
__device__ __half g_V[(size_t)TOK * D_];                // V rows fp16 (64MB)
__device__ float  g_scores[(size_t)NH * TOK];           // raw per-head Q.K dots
__device__ float  g_out[(size_t)B_ * D_];
__device__ float  g_proj[(size_t)B_ * D_];
__device__ int    g_perm_e[TOK];
__device__ int    g_perm_u[B_];
__device__ int    g_hist_e[NT], g_fill_e[NT];
__device__ int    g_hist_u[NT], g_fill_u[NT];

// ---------------- prep: weight transpose fp32[k][n] -> fp16[n][k] + counter zero ----------------
__global__ void k_wt(const float* Wq, const float* Wk, const float* Wv) {
    int z = blockIdx.z;
    int matt = z >> 2;
    int e = z & 3;
    if (blockIdx.x == 0 && blockIdx.y == 0 && z == 0) {
        int i = threadIdx.y * 32 + threadIdx.x;
        if (i < NT) { g_hist_e[i] = 0; g_fill_e[i] = 0; g_hist_u[i] = 0; g_fill_u[i] = 0; }
    }
    const float* src = ((matt == 0) ? Wq : (matt == 1) ? Wk : Wv) + (size_t)e * WSZ;
    __half* dst = g_W16 + ((size_t)matt * NT + e) * WSZ;
    __shared__ float t[32][33];
    int k0 = blockIdx.y * 32;
    int n0 = blockIdx.x * 32;
    int tx = threadIdx.x;
    int ty = threadIdx.y;
#pragma unroll
    for (int i = 0; i < 32; i += 8) {
        t[ty + i][tx] = src[(size_t)(k0 + ty + i) * 256 + n0 + tx];
    }
    __syncthreads();
#pragma unroll
    for (int i = 0; i < 32; i += 8) {
        dst[(size_t)(n0 + ty + i) * 256 + k0 + tx] = __float2half(t[tx][ty + i]);
    }
}

// ---------------- histogram (both label arrays in one kernel) ----------------
__global__ void k_hist2(const int* et, const int* ut) {
    __shared__ int he[NT], hu[NT];
    int tid = threadIdx.x;
    if (tid < NT) { he[tid] = 0; hu[tid] = 0; }
    __syncthreads();
    int i = blockIdx.x * blockDim.x + tid;
    if (i < TOK) atomicAdd(&he[et[i]], 1);
    if (i < B_) atomicAdd(&hu[ut[i]], 1);
    __syncthreads();
    if (tid < NT) {
        if (he[tid] > 0) atomicAdd(&g_hist_e[tid], he[tid]);
        if (hu[tid] > 0) atomicAdd(&g_hist_u[tid], hu[tid]);
    }
}

// ---------------- permutation assignment (bases computed locally from hist) ----------------
__global__ void k_assign2(const int* et, const int* ut) {
    __shared__ int he[NT], le[NT], hu[NT], lu[NT];
    int tid = threadIdx.x;
    if (tid < NT) { he[tid] = 0; hu[tid] = 0; }
    __syncthreads();
    int i = blockIdx.x * blockDim.x + tid;
    int e1 = 0, p1 = 0, u1 = 0, p2 = 0;
    if (i < TOK) { e1 = et[i]; p1 = atomicAdd(&he[e1], 1); }
    if (i < B_) { u1 = ut[i]; p2 = atomicAdd(&hu[u1], 1); }
    __syncthreads();
    if (tid < NT) {
        le[tid] = (he[tid] > 0) ? atomicAdd(&g_fill_e[tid], he[tid]) : 0;
        lu[tid] = (hu[tid] > 0) ? atomicAdd(&g_fill_u[tid], hu[tid]) : 0;
    }
    __syncthreads();
    if (i < TOK) {
        int be = 0;
        for (int j = 0; j < NT; j++) { if (j < e1) be += g_hist_e[j]; }
        g_perm_e[be + le[e1] + p1] = i;
    }
    if (i < B_) {
        int bu = 0;
        for (int j = 0; j < NT; j++) { if (j < u1) bu += g_hist_u[j]; }
        g_perm_u[bu + lu[u1] + p2] = i;
    }
}

// ---------------- fused QKV GEMM + score epilogue (fp16 mma.sync, pipelined) ----------------
// grid (2, NT, 2048); block 256 (8 warps). CTA tile: M=64 tokens, N=128 cols (x half),
// K=256 (8 chunks of 32), 3 mats. Warp tile 32x32 => one head per warp column group.
// Q pass result parked in smem (fp16). occ-4 forced: 64 regs -> 32 warps/SM.
__global__ void __launch_bounds__(256, 4) k_fused(const float* q, const float* k, const float* v) {
    const int z = blockIdx.x;
    const int e = blockIdx.y;
    const int cnt = g_hist_e[e];
    const int row0 = blockIdx.z * 64;
    if (row0 >= cnt) return;

    __shared__ __half As[2][64][BPAD];
    __shared__ __half Bs[2][128][BPAD];
    __shared__ unsigned int Qs[16][256];   // per-thread Q result, packed half2, conflict-free
    __shared__ int toks[64];

    const int tid = threadIdx.x;
    if (tid < 64) {
        int base = 0;
        for (int j = 0; j < NT; j++) { if (j < e) base += g_hist_e[j]; }
        int r = row0 + tid;
        toks[tid] = (r < cnt) ? g_perm_e[base + r] : -1;
    }
    __syncthreads();

    const int lane = tid & 31, warp = tid >> 5;
    const int wm = warp & 1, wn = warp >> 1;   // wn in 0..3: 32-col group = head (z*4+wn)

    // shared 32-bit addresses for cp.async / ldmatrix
    unsigned long long t64a, t64b;
    asm("cvta.to.shared.u64 %0, %1;" : "=l"(t64a) : "l"((const void*)&As[0][0][0]));
    asm("cvta.to.shared.u64 %0, %1;" : "=l"(t64b) : "l"((const void*)&Bs[0][0][0]));
    const unsigned int aS = (unsigned int)t64a;
    const unsigned int bS = (unsigned int)t64b;

    // staging thread mapping
    const int arow = tid >> 2;          // 0..63
    const int q4 = tid & 3;             // 0..3 -> 8 halves each

    float acc[2][4][4];
    const int tk = toks[arow];

    for (int mat = 0; mat < 3; mat++) {
        const float* A = (mat == 0) ? q : (mat == 1) ? k : v;
        const __half* W = g_W16 + ((size_t)mat * NT + e) * WSZ + (size_t)z * 128 * 256;

#pragma unroll
        for (int a1 = 0; a1 < 2; a1++)
#pragma unroll
            for (int a2 = 0; a2 < 4; a2++)
#pragma unroll
                for (int a3 = 0; a3 < 4; a3++) acc[a1][a2][a3] = 0.f;

        // ---- prologue: chunk 0 ----
        float4 fA0 = make_float4(0.f, 0.f, 0.f, 0.f), fA1 = fA0;
        if (tk >= 0) {
            const float4* p = (const float4*)(A + (size_t)tk * D_ + q4 * 8);
            fA0 = p[0]; fA1 = p[1];
        }
#pragma unroll
        for (int it = 0; it < 2; it++) {
            int idx = it * 256 + tid;
            int n = idx >> 2;
            int kq = idx & 3;
            unsigned int dst = bS + n * (BPAD * 2) + kq * 16;
            const void* src = (const void*)(W + (size_t)n * 256 + kq * 8);
            asm volatile("cp.async.ca.shared.global [%0], [%1], 16;" :: "r"(dst), "l"(src) : "memory");
        }
        asm volatile("cp.async.commit_group;" ::: "memory");
        {
            __half2 h0 = __floats2half2_rn(fA0.x, fA0.y);
            __half2 h1 = __floats2half2_rn(fA0.z, fA0.w);
            __half2 h2 = __floats2half2_rn(fA1.x, fA1.y);
            __half2 h3 = __floats2half2_rn(fA1.z, fA1.w);
            uint4 sv;
            sv.x = *(unsigned int*)&h0; sv.y = *(unsigned int*)&h1;
            sv.z = *(unsigned int*)&h2; sv.w = *(unsigned int*)&h3;
            *(uint4*)&As[0][arow][q4 * 8] = sv;
        }
        asm volatile("cp.async.wait_group 0;" ::: "memory");
        __syncthreads();

        int buf = 0;
        for (int c = 0; c < 8; c++) {
            if (c < 7) {
                int kc = (c + 1) * 32;
                fA0 = make_float4(0.f, 0.f, 0.f, 0.f); fA1 = fA0;
                if (tk >= 0) {
                    const float4* p = (const float4*)(A + (size_t)tk * D_ + kc + q4 * 8);
                    fA0 = p[0]; fA1 = p[1];
                }
                unsigned int bdst = bS + (buf ^ 1) * 10240;
#pragma unroll
                for (int it = 0; it < 2; it++) {
                    int idx = it * 256 + tid;
                    int n = idx >> 2;
                    int kq = idx & 3;
                    unsigned int dst = bdst + n * (BPAD * 2) + kq * 16;
                    const void* src = (const void*)(W + (size_t)n * 256 + kc + kq * 8);
                    asm volatile("cp.async.ca.shared.global [%0], [%1], 16;" :: "r"(dst), "l"(src) : "memory");
                }
                asm volatile("cp.async.commit_group;" ::: "memory");
            }

            // ---- MMAs on current buffer (ldmatrix fragments) ----
            unsigned int abase = aS + buf * 5120;
            unsigned int bbase = bS + buf * 10240;
#pragma unroll
            for (int k16 = 0; k16 < 2; k16++) {
                unsigned int coff = (k16 * 16 + (lane >> 4) * 8) * 2;
                unsigned int a0[4], a1r[4];
                {
                    unsigned int addr = abase + (wm * 32 + (lane & 15)) * (BPAD * 2) + coff;
                    asm volatile("ldmatrix.sync.aligned.m8n8.x4.shared.b16 {%0,%1,%2,%3}, [%4];"
                                 : "=r"(a0[0]), "=r"(a0[1]), "=r"(a0[2]), "=r"(a0[3]) : "r"(addr));
                }
                {
                    unsigned int addr = abase + (wm * 32 + 16 + (lane & 15)) * (BPAD * 2) + coff;
                    asm volatile("ldmatrix.sync.aligned.m8n8.x4.shared.b16 {%0,%1,%2,%3}, [%4];"
                                 : "=r"(a1r[0]), "=r"(a1r[1]), "=r"(a1r[2]), "=r"(a1r[3]) : "r"(addr));
                }
#pragma unroll
                for (int nb = 0; nb < 2; nb++) {
                    unsigned int b0[4];
                    unsigned int addr = bbase + (wn * 32 + nb * 16 + (lane & 15)) * (BPAD * 2) + coff;
                    asm volatile("ldmatrix.sync.aligned.m8n8.x4.shared.b16 {%0,%1,%2,%3}, [%4];"
                                 : "=r"(b0[0]), "=r"(b0[1]), "=r"(b0[2]), "=r"(b0[3]) : "r"(addr));
                    asm volatile(
                        "mma.sync.aligned.m16n8k16.row.col.f32.f16.f16.f32 "
                        "{%0,%1,%2,%3},{%4,%5,%6,%7},{%8,%9},{%0,%1,%2,%3};"
                        : "+f"(acc[0][nb * 2][0]), "+f"(acc[0][nb * 2][1]),
                          "+f"(acc[0][nb * 2][2]), "+f"(acc[0][nb * 2][3])
                        : "r"(a0[0]), "r"(a0[1]), "r"(a0[2]), "r"(a0[3]),
                          "r"(b0[0]), "r"(b0[2]));
                    asm volatile(
                        "mma.sync.aligned.m16n8k16.row.col.f32.f16.f16.f32 "
                        "{%0,%1,%2,%3},{%4,%5,%6,%7},{%8,%9},{%0,%1,%2,%3};"
                        : "+f"(acc[0][nb * 2 + 1][0]), "+f"(acc[0][nb * 2 + 1][1]),
                          "+f"(acc[0][nb * 2 + 1][2]), "+f"(acc[0][nb * 2 + 1][3])
                        : "r"(a0[0]), "r"(a0[1]), "r"(a0[2]), "r"(a0[3]),
                          "r"(b0[1]), "r"(b0[3]));
                    asm volatile(
                        "mma.sync.aligned.m16n8k16.row.col.f32.f16.f16.f32 "
                        "{%0,%1,%2,%3},{%4,%5,%6,%7},{%8,%9},{%0,%1,%2,%3};"
                        : "+f"(acc[1][nb * 2][0]), "+f"(acc[1][nb * 2][1]),
                          "+f"(acc[1][nb * 2][2]), "+f"(acc[1][nb * 2][3])
                        : "r"(a1r[0]), "r"(a1r[1]), "r"(a1r[2]), "r"(a1r[3]),
                          "r"(b0[0]), "r"(b0[2]));
                    asm volatile(
                        "mma.sync.aligned.m16n8k16.row.col.f32.f16.f16.f32 "
                        "{%0,%1,%2,%3},{%4,%5,%6,%7},{%8,%9},{%0,%1,%2,%3};"
                        : "+f"(acc[1][nb * 2 + 1][0]), "+f"(acc[1][nb * 2 + 1][1]),
                          "+f"(acc[1][nb * 2 + 1][2]), "+f"(acc[1][nb * 2 + 1][3])
                        : "r"(a1r[0]), "r"(a1r[1]), "r"(a1r[2]), "r"(a1r[3]),
                          "r"(b0[1]), "r"(b0[3]));
                }
            }

            if (c < 7) {
                __half2 h0 = __floats2half2_rn(fA0.x, fA0.y);
                __half2 h1 = __floats2half2_rn(fA0.z, fA0.w);
                __half2 h2 = __floats2half2_rn(fA1.x, fA1.y);
                __half2 h3 = __floats2half2_rn(fA1.z, fA1.w);
                uint4 sv;
                sv.x = *(unsigned int*)&h0; sv.y = *(unsigned int*)&h1;
                sv.z = *(unsigned int*)&h2; sv.w = *(unsigned int*)&h3;
                *(uint4*)&As[buf ^ 1][arow][q4 * 8] = sv;
            }
            asm volatile("cp.async.wait_group 0;" ::: "memory");
            __syncthreads();
            buf ^= 1;
        }

        // ---------------- per-mat epilogue ----------------
        if (mat == 0) {
            // park Q result in smem as half2, thread-local layout Qs[i][tid]
#pragma unroll
            for (int mt = 0; mt < 2; mt++)
#pragma unroll
                for (int nt = 0; nt < 4; nt++) {
                    __half2 p0 = __floats2half2_rn(acc[mt][nt][0], acc[mt][nt][1]);
                    __half2 p1 = __floats2half2_rn(acc[mt][nt][2], acc[mt][nt][3]);
                    Qs[mt * 8 + nt * 2 + 0][tid] = *(unsigned int*)&p0;
                    Qs[mt * 8 + nt * 2 + 1][tid] = *(unsigned int*)&p1;
                }
        } else if (mat == 1) {
            float part[2][2];
#pragma unroll
            for (int mt = 0; mt < 2; mt++) {
                part[mt][0] = 0.f;
                part[mt][1] = 0.f;
            }
#pragma unroll
            for (int mt = 0; mt < 2; mt++)
#pragma unroll
                for (int nt = 0; nt < 4; nt++) {
                    unsigned int u0 = Qs[mt * 8 + nt * 2 + 0][tid];
                    unsigned int u1 = Qs[mt * 8 + nt * 2 + 1][tid];
                    float2 q0 = __half22float2(*(__half2*)&u0);
                    float2 q1 = __half22float2(*(__half2*)&u1);
                    part[mt][0] += q0.x * acc[mt][nt][0] + q0.y * acc[mt][nt][1];
                    part[mt][1] += q1.x * acc[mt][nt][2] + q1.y * acc[mt][nt][3];
                }
#pragma unroll
            for (int mt = 0; mt < 2; mt++)
#pragma unroll
                for (int rr = 0; rr < 2; rr++) {
                    float vv = part[mt][rr];
                    vv += __shfl_xor_sync(0xffffffffu, vv, 1);
                    vv += __shfl_xor_sync(0xffffffffu, vv, 2);
                    part[mt][rr] = vv;
                }
            if ((lane & 3) == 0) {
                int rb = wm * 32 + (lane >> 2);
                int h = z * 4 + wn;
#pragma unroll
                for (int mt = 0; mt < 2; mt++)
#pragma unroll
                    for (int rr = 0; rr < 2; rr++) {
                        int r = rb + mt * 16 + rr * 8;
                        int t = toks[r];
                        if (t >= 0) {
                            g_scores[(size_t)h * TOK + t] = part[mt][rr];
                        }
                    }
            }
        } else {
#pragma unroll
            for (int mt = 0; mt < 2; mt++) {
                int rl = wm * 32 + mt * 16 + (lane >> 2);
                int t0 = toks[rl], t1 = toks[rl + 8];
#pragma unroll
                for (int nt = 0; nt < 4; nt++) {
                    int col = z * 128 + wn * 32 + nt * 8 + (lane & 3) * 2;
                    if (t0 >= 0) {
                        *(__half2*)(g_V + (size_t)t0 * D_ + col) = __floats2half2_rn(acc[mt][nt][0], acc[mt][nt][1]);
                    }
                    if (t1 >= 0) {
                        *(__half2*)(g_V + (size_t)t1 * D_ + col) = __floats2half2_rn(acc[mt][nt][2], acc[mt][nt][3]);
                    }
                }
            }
        }
    }
}

// ---------------- attention per batch ----------------
__global__ void __launch_bounds__(256) k_attn(const float* rel_pri, const int* et, const int* ut,
                                              const int* mask, float* dout) {
    int b = blockIdx.x, tid = threadIdx.x, lane = tid & 31, w = tid >> 5;
    __shared__ float attn_s[NH][32];

    int u = ut[b];
    int tok = b * 32 + lane;
    float s = g_scores[(size_t)w * TOK + tok];
    float pri = rel_pri[u * NT + et[tok]];
    s = s * pri * 0.17677669529663689f;   // 1/sqrt(32)
    if (mask[tok] != 0) s = -1e10f;

    float mx = s;
#pragma unroll
    for (int o = 16; o; o >>= 1) mx = fmaxf(mx, __shfl_xor_sync(0xffffffffu, mx, o));
    float ex = expf(s - mx), sm = ex;
#pragma unroll
    for (int o = 16; o; o >>= 1) sm += __shfl_xor_sync(0xffffffffu, sm, o);
    float a = ex / sm;
    attn_s[w][lane] = a;
    dout[(size_t)B_ * D_ + ((size_t)w * B_ + b) * 32 + lane] = a;   // attn_flat
    __syncthreads();

    const __half* Vg = g_V + (size_t)b * 32 * D_;
    float o2 = 0.f;
#pragma unroll
    for (int nn = 0; nn < 32; nn++)
        o2 += attn_s[w][nn] * __half2float(Vg[nn * D_ + w * 32 + lane]);
    g_out[(size_t)b * D_ + tid] = o2;
}

// ---------------- grouped FC projection (by utype) ----------------
__global__ void __launch_bounds__(256) k_proj(const float* fc_w, const float* fc_b) {
    int u = blockIdx.y;
    int cnt = g_hist_u[u];
    int r0 = blockIdx.x * 32;
    if (r0 >= cnt) return;

    __shared__ float outs[32][257];
    __shared__ int bidx[32];
    int tid = threadIdx.x;
    if (tid < 32) {
        int base = 0;
        for (int j = 0; j < NT; j++) { if (j < u) base += g_hist_u[j]; }
        int r = r0 + tid;
        bidx[tid] = (r < cnt) ? g_perm_u[base + r] : -1;
    }
    __syncthreads();
    for (int i = tid; i < 32 * 256; i += 256) {
        int row = i >> 8, c = i & 255;
        int bb = bidx[row];
        outs[row][c] = (bb >= 0) ? g_out[(size_t)bb * D_ + c] : 0.f;
    }
    __syncthreads();

    int tj = tid & 63, tr = tid >> 6;
    int j0 = tj * 4, bb0 = tr * 8;
    float acc[8][4];
#pragma unroll
    for (int r = 0; r < 8; r++) {
        acc[r][0] = fc_b[u * D_ + j0 + 0];
        acc[r][1] = fc_b[u * D_ + j0 + 1];
        acc[r][2] = fc_b[u * D_ + j0 + 2];
        acc[r][3] = fc_b[u * D_ + j0 + 3];
    }
    const float4* fw = (const float4*)(fc_w + (size_t)u * WSZ + j0);
    for (int i = 0; i < 256; i++) {
        float4 f = fw[(size_t)i * 64];
#pragma unroll
        for (int r = 0; r < 8; r++) {
            float ov = outs[bb0 + r][i];
            acc[r][0] = fmaf(ov, f.x, acc[r][0]);
            acc[r][1] = fmaf(ov, f.y, acc[r][1]);
            acc[r][2] = fmaf(ov, f.z, acc[r][2]);
            acc[r][3] = fmaf(ov, f.w, acc[r][3]);
        }
    }
#pragma unroll
    for (int r = 0; r < 8; r++) {
        int bb = bidx[bb0 + r];
        if (bb >= 0) {
            float4 st = make_float4(acc[r][0], acc[r][1], acc[r][2], acc[r][3]);
            *(float4*)(g_proj + (size_t)bb * D_ + j0) = st;
        }
    }
}

// ---------------- LayerNorm ----------------
__global__ void __launch_bounds__(256) k_ln(const float* gamma, const float* beta, float* dout) {
    int b = blockIdx.x, tid = threadIdx.x, lane = tid & 31, w = tid >> 5;
    float p = g_proj[(size_t)b * D_ + tid];
    __shared__ float red[8];
    __shared__ float bc;

    float x = p;
#pragma unroll
    for (int o = 16; o; o >>= 1) x += __shfl_xor_sync(0xffffffffu, x, o);
    if (lane == 0) red[w] = x;
    __syncthreads();
    if (tid == 0) {
        float ss = 0.f;
        for (int i = 0; i < 8; i++) ss += red[i];
        bc = ss * (1.f / 256.f);
    }
    __syncthreads();
    float mu = bc;
    float dd = p - mu;
    __syncthreads();

    x = dd * dd;
#pragma unroll
    for (int o = 16; o; o >>= 1) x += __shfl_xor_sync(0xffffffffu, x, o);
    if (lane == 0) red[w] = x;
    __syncthreads();
    if (tid == 0) {
        float ss = 0.f;
        for (int i = 0; i < 8; i++) ss += red[i];
        bc = rsqrtf(ss * (1.f / 256.f) + 1e-5f);
    }
    __syncthreads();
    dout[(size_t)b * D_ + tid] = dd * bc * gamma[tid] + beta[tid];
}

// ---------------- launch ----------------
extern "C" void kernel_launch(void* const* d_in, const int* in_sizes, int n_in,
                              void* d_out, int out_size) {
    const float* q        = (const float*)d_in[0];
    const float* k        = (const float*)d_in[1];
    const float* v        = (const float*)d_in[2];
    const float* Wq       = (const float*)d_in[3];
    const float* Wk       = (const float*)d_in[4];
    const float* Wv       = (const float*)d_in[5];
    const float* rel_pri  = (const float*)d_in[6];
    const float* fc_w     = (const float*)d_in[7];
    const float* fc_b     = (const float*)d_in[8];
    const float* gamma    = (const float*)d_in[9];
    const float* beta     = (const float*)d_in[10];
    const int*   et       = (const int*)d_in[11];
    const int*   ut       = (const int*)d_in[12];
    const int*   mask     = (const int*)d_in[13];
    float* out = (float*)d_out;

    k_wt<<<dim3(8, 8, 12), dim3(32, 8)>>>(Wq, Wk, Wv);
    k_hist2<<<512, 256>>>(et, ut);
    k_assign2<<<512, 256>>>(et, ut);
    k_fused<<<dim3(2, NT, 2048), 256>>>(q, k, v);
    k_attn<<<B_, 256>>>(rel_pri, et, ut, mask, out);
    k_proj<<<dim3(48, NT), 256>>>(fc_w, fc_b);
    k_ln<<<B_, 256>>>(gamma, beta, out);
}

// round 14
// speedup vs baseline: 1.1785x; 1.1785x over previous
#include <cuda_runtime.h>
#include <cuda_fp16.h>
#include <math.h>

#define B_   4096
#define N_   32
#define D_   256
#define NT   4
#define NH   8
#define TOK  131072
#define WSZ  65536
#define BPAD 40

// ---------------- scratch (static device allocations) ----------------
__device__ __half g_W16[(size_t)3 * NT * WSZ];          // W^T: [mat][e][n][k] fp16
__device__ __half g_V[(size_t)TOK * D_];                // V rows fp16 (64MB)
__device__ float  g_scores[(size_t)NH * TOK];           // raw per-head Q.K dots
__device__ float  g_out[(size_t)B_ * D_];
__device__ int    g_perm_e[TOK];
__device__ int    g_perm_u[B_];
__device__ int    g_hist_e[NT], g_fill_e[NT];
__device__ int    g_hist_u[NT], g_fill_u[NT];

// ---------------- prep: weight transpose fp32[k][n] -> fp16[n][k] + counter zero ----------------
__global__ void k_wt(const float* Wq, const float* Wk, const float* Wv) {
    int z = blockIdx.z;
    int matt = z >> 2;
    int e = z & 3;
    if (blockIdx.x == 0 && blockIdx.y == 0 && z == 0) {
        int i = threadIdx.y * 32 + threadIdx.x;
        if (i < NT) { g_hist_e[i] = 0; g_fill_e[i] = 0; g_hist_u[i] = 0; g_fill_u[i] = 0; }
    }
    const float* src = ((matt == 0) ? Wq : (matt == 1) ? Wk : Wv) + (size_t)e * WSZ;
    __half* dst = g_W16 + ((size_t)matt * NT + e) * WSZ;
    __shared__ float t[32][33];
    int k0 = blockIdx.y * 32;
    int n0 = blockIdx.x * 32;
    int tx = threadIdx.x;
    int ty = threadIdx.y;
#pragma unroll
    for (int i = 0; i < 32; i += 8) {
        t[ty + i][tx] = src[(size_t)(k0 + ty + i) * 256 + n0 + tx];
    }
    __syncthreads();
#pragma unroll
    for (int i = 0; i < 32; i += 8) {
        dst[(size_t)(n0 + ty + i) * 256 + k0 + tx] = __float2half(t[tx][ty + i]);
    }
}

// ---------------- histogram (both label arrays in one kernel) ----------------
__global__ void k_hist2(const int* et, const int* ut) {
    __shared__ int he[NT], hu[NT];
    int tid = threadIdx.x;
    if (tid < NT) { he[tid] = 0; hu[tid] = 0; }
    __syncthreads();
    int i = blockIdx.x * blockDim.x + tid;
    if (i < TOK) atomicAdd(&he[et[i]], 1);
    if (i < B_) atomicAdd(&hu[ut[i]], 1);
    __syncthreads();
    if (tid < NT) {
        if (he[tid] > 0) atomicAdd(&g_hist_e[tid], he[tid]);
        if (hu[tid] > 0) atomicAdd(&g_hist_u[tid], hu[tid]);
    }
}

// ---------------- permutation assignment (bases computed locally from hist) ----------------
__global__ void k_assign2(const int* et, const int* ut) {
    __shared__ int he[NT], le[NT], hu[NT], lu[NT];
    int tid = threadIdx.x;
    if (tid < NT) { he[tid] = 0; hu[tid] = 0; }
    __syncthreads();
    int i = blockIdx.x * blockDim.x + tid;
    int e1 = 0, p1 = 0, u1 = 0, p2 = 0;
    if (i < TOK) { e1 = et[i]; p1 = atomicAdd(&he[e1], 1); }
    if (i < B_) { u1 = ut[i]; p2 = atomicAdd(&hu[u1], 1); }
    __syncthreads();
    if (tid < NT) {
        le[tid] = (he[tid] > 0) ? atomicAdd(&g_fill_e[tid], he[tid]) : 0;
        lu[tid] = (hu[tid] > 0) ? atomicAdd(&g_fill_u[tid], hu[tid]) : 0;
    }
    __syncthreads();
    if (i < TOK) {
        int be = 0;
        for (int j = 0; j < NT; j++) { if (j < e1) be += g_hist_e[j]; }
        g_perm_e[be + le[e1] + p1] = i;
    }
    if (i < B_) {
        int bu = 0;
        for (int j = 0; j < NT; j++) { if (j < u1) bu += g_hist_u[j]; }
        g_perm_u[bu + lu[u1] + p2] = i;
    }
}

// ---------------- fused QKV GEMM + score epilogue (fp16 mma.sync, pipelined) ----------------
// grid (2, NT, 2048); block 256 (8 warps). CTA tile: M=64 tokens, N=128 cols (x half),
// K=256 (8 chunks of 32), 3 mats. Warp tile 32x32 => one head per warp column group.
// Q pass result parked in smem (fp16). occ-3: regs 79 (R12 sweet spot).
__global__ void __launch_bounds__(256, 3) k_fused(const float* q, const float* k, const float* v) {
    const int z = blockIdx.x;
    const int e = blockIdx.y;
    const int cnt = g_hist_e[e];
    const int row0 = blockIdx.z * 64;
    if (row0 >= cnt) return;

    __shared__ __half As[2][64][BPAD];
    __shared__ __half Bs[2][128][BPAD];
    __shared__ unsigned int Qs[16][256];   // per-thread Q result, packed half2, conflict-free
    __shared__ int toks[64];

    const int tid = threadIdx.x;
    if (tid < 64) {
        int base = 0;
        for (int j = 0; j < NT; j++) { if (j < e) base += g_hist_e[j]; }
        int r = row0 + tid;
        toks[tid] = (r < cnt) ? g_perm_e[base + r] : -1;
    }
    __syncthreads();

    const int lane = tid & 31, warp = tid >> 5;
    const int wm = warp & 1, wn = warp >> 1;   // wn in 0..3: 32-col group = head (z*4+wn)

    // shared 32-bit addresses for cp.async / ldmatrix
    unsigned long long t64a, t64b;
    asm("cvta.to.shared.u64 %0, %1;" : "=l"(t64a) : "l"((const void*)&As[0][0][0]));
    asm("cvta.to.shared.u64 %0, %1;" : "=l"(t64b) : "l"((const void*)&Bs[0][0][0]));
    const unsigned int aS = (unsigned int)t64a;
    const unsigned int bS = (unsigned int)t64b;

    // staging thread mapping
    const int arow = tid >> 2;          // 0..63
    const int q4 = tid & 3;             // 0..3 -> 8 halves each

    float acc[2][4][4];
    const int tk = toks[arow];

    for (int mat = 0; mat < 3; mat++) {
        const float* A = (mat == 0) ? q : (mat == 1) ? k : v;
        const __half* W = g_W16 + ((size_t)mat * NT + e) * WSZ + (size_t)z * 128 * 256;

#pragma unroll
        for (int a1 = 0; a1 < 2; a1++)
#pragma unroll
            for (int a2 = 0; a2 < 4; a2++)
#pragma unroll
                for (int a3 = 0; a3 < 4; a3++) acc[a1][a2][a3] = 0.f;

        // ---- prologue: chunk 0 ----
        float4 fA0 = make_float4(0.f, 0.f, 0.f, 0.f), fA1 = fA0;
        if (tk >= 0) {
            const float4* p = (const float4*)(A + (size_t)tk * D_ + q4 * 8);
            fA0 = p[0]; fA1 = p[1];
        }
#pragma unroll
        for (int it = 0; it < 2; it++) {
            int idx = it * 256 + tid;
            int n = idx >> 2;
            int kq = idx & 3;
            unsigned int dst = bS + n * (BPAD * 2) + kq * 16;
            const void* src = (const void*)(W + (size_t)n * 256 + kq * 8);
            asm volatile("cp.async.ca.shared.global [%0], [%1], 16;" :: "r"(dst), "l"(src) : "memory");
        }
        asm volatile("cp.async.commit_group;" ::: "memory");
        {
            __half2 h0 = __floats2half2_rn(fA0.x, fA0.y);
            __half2 h1 = __floats2half2_rn(fA0.z, fA0.w);
            __half2 h2 = __floats2half2_rn(fA1.x, fA1.y);
            __half2 h3 = __floats2half2_rn(fA1.z, fA1.w);
            uint4 sv;
            sv.x = *(unsigned int*)&h0; sv.y = *(unsigned int*)&h1;
            sv.z = *(unsigned int*)&h2; sv.w = *(unsigned int*)&h3;
            *(uint4*)&As[0][arow][q4 * 8] = sv;
        }
        asm volatile("cp.async.wait_group 0;" ::: "memory");
        __syncthreads();

        int buf = 0;
        for (int c = 0; c < 8; c++) {
            if (c < 7) {
                int kc = (c + 1) * 32;
                fA0 = make_float4(0.f, 0.f, 0.f, 0.f); fA1 = fA0;
                if (tk >= 0) {
                    const float4* p = (const float4*)(A + (size_t)tk * D_ + kc + q4 * 8);
                    fA0 = p[0]; fA1 = p[1];
                }
                unsigned int bdst = bS + (buf ^ 1) * 10240;
#pragma unroll
                for (int it = 0; it < 2; it++) {
                    int idx = it * 256 + tid;
                    int n = idx >> 2;
                    int kq = idx & 3;
                    unsigned int dst = bdst + n * (BPAD * 2) + kq * 16;
                    const void* src = (const void*)(W + (size_t)n * 256 + kc + kq * 8);
                    asm volatile("cp.async.ca.shared.global [%0], [%1], 16;" :: "r"(dst), "l"(src) : "memory");
                }
                asm volatile("cp.async.commit_group;" ::: "memory");
            }

            // ---- MMAs on current buffer (ldmatrix fragments) ----
            unsigned int abase = aS + buf * 5120;
            unsigned int bbase = bS + buf * 10240;
#pragma unroll
            for (int k16 = 0; k16 < 2; k16++) {
                unsigned int coff = (k16 * 16 + (lane >> 4) * 8) * 2;
                unsigned int a0[4], a1r[4];
                {
                    unsigned int addr = abase + (wm * 32 + (lane & 15)) * (BPAD * 2) + coff;
                    asm volatile("ldmatrix.sync.aligned.m8n8.x4.shared.b16 {%0,%1,%2,%3}, [%4];"
                                 : "=r"(a0[0]), "=r"(a0[1]), "=r"(a0[2]), "=r"(a0[3]) : "r"(addr));
                }
                {
                    unsigned int addr = abase + (wm * 32 + 16 + (lane & 15)) * (BPAD * 2) + coff;
                    asm volatile("ldmatrix.sync.aligned.m8n8.x4.shared.b16 {%0,%1,%2,%3}, [%4];"
                                 : "=r"(a1r[0]), "=r"(a1r[1]), "=r"(a1r[2]), "=r"(a1r[3]) : "r"(addr));
                }
#pragma unroll
                for (int nb = 0; nb < 2; nb++) {
                    unsigned int b0[4];
                    unsigned int addr = bbase + (wn * 32 + nb * 16 + (lane & 15)) * (BPAD * 2) + coff;
                    asm volatile("ldmatrix.sync.aligned.m8n8.x4.shared.b16 {%0,%1,%2,%3}, [%4];"
                                 : "=r"(b0[0]), "=r"(b0[1]), "=r"(b0[2]), "=r"(b0[3]) : "r"(addr));
                    asm volatile(
                        "mma.sync.aligned.m16n8k16.row.col.f32.f16.f16.f32 "
                        "{%0,%1,%2,%3},{%4,%5,%6,%7},{%8,%9},{%0,%1,%2,%3};"
                        : "+f"(acc[0][nb * 2][0]), "+f"(acc[0][nb * 2][1]),
                          "+f"(acc[0][nb * 2][2]), "+f"(acc[0][nb * 2][3])
                        : "r"(a0[0]), "r"(a0[1]), "r"(a0[2]), "r"(a0[3]),
                          "r"(b0[0]), "r"(b0[2]));
                    asm volatile(
                        "mma.sync.aligned.m16n8k16.row.col.f32.f16.f16.f32 "
                        "{%0,%1,%2,%3},{%4,%5,%6,%7},{%8,%9},{%0,%1,%2,%3};"
                        : "+f"(acc[0][nb * 2 + 1][0]), "+f"(acc[0][nb * 2 + 1][1]),
                          "+f"(acc[0][nb * 2 + 1][2]), "+f"(acc[0][nb * 2 + 1][3])
                        : "r"(a0[0]), "r"(a0[1]), "r"(a0[2]), "r"(a0[3]),
                          "r"(b0[1]), "r"(b0[3]));
                    asm volatile(
                        "mma.sync.aligned.m16n8k16.row.col.f32.f16.f16.f32 "
                        "{%0,%1,%2,%3},{%4,%5,%6,%7},{%8,%9},{%0,%1,%2,%3};"
                        : "+f"(acc[1][nb * 2][0]), "+f"(acc[1][nb * 2][1]),
                          "+f"(acc[1][nb * 2][2]), "+f"(acc[1][nb * 2][3])
                        : "r"(a1r[0]), "r"(a1r[1]), "r"(a1r[2]), "r"(a1r[3]),
                          "r"(b0[0]), "r"(b0[2]));
                    asm volatile(
                        "mma.sync.aligned.m16n8k16.row.col.f32.f16.f16.f32 "
                        "{%0,%1,%2,%3},{%4,%5,%6,%7},{%8,%9},{%0,%1,%2,%3};"
                        : "+f"(acc[1][nb * 2 + 1][0]), "+f"(acc[1][nb * 2 + 1][1]),
                          "+f"(acc[1][nb * 2 + 1][2]), "+f"(acc[1][nb * 2 + 1][3])
                        : "r"(a1r[0]), "r"(a1r[1]), "r"(a1r[2]), "r"(a1r[3]),
                          "r"(b0[1]), "r"(b0[3]));
                }
            }

            if (c < 7) {
                __half2 h0 = __floats2half2_rn(fA0.x, fA0.y);
                __half2 h1 = __floats2half2_rn(fA0.z, fA0.w);
                __half2 h2 = __floats2half2_rn(fA1.x, fA1.y);
                __half2 h3 = __floats2half2_rn(fA1.z, fA1.w);
                uint4 sv;
                sv.x = *(unsigned int*)&h0; sv.y = *(unsigned int*)&h1;
                sv.z = *(unsigned int*)&h2; sv.w = *(unsigned int*)&h3;
                *(uint4*)&As[buf ^ 1][arow][q4 * 8] = sv;
            }
            asm volatile("cp.async.wait_group 0;" ::: "memory");
            __syncthreads();
            buf ^= 1;
        }

        // ---------------- per-mat epilogue ----------------
        if (mat == 0) {
            // park Q result in smem as half2, thread-local layout Qs[i][tid]
#pragma unroll
            for (int mt = 0; mt < 2; mt++)
#pragma unroll
                for (int nt = 0; nt < 4; nt++) {
                    __half2 p0 = __floats2half2_rn(acc[mt][nt][0], acc[mt][nt][1]);
                    __half2 p1 = __floats2half2_rn(acc[mt][nt][2], acc[mt][nt][3]);
                    Qs[mt * 8 + nt * 2 + 0][tid] = *(unsigned int*)&p0;
                    Qs[mt * 8 + nt * 2 + 1][tid] = *(unsigned int*)&p1;
                }
        } else if (mat == 1) {
            float part[2][2];
#pragma unroll
            for (int mt = 0; mt < 2; mt++) {
                part[mt][0] = 0.f;
                part[mt][1] = 0.f;
            }
#pragma unroll
            for (int mt = 0; mt < 2; mt++)
#pragma unroll
                for (int nt = 0; nt < 4; nt++) {
                    unsigned int u0 = Qs[mt * 8 + nt * 2 + 0][tid];
                    unsigned int u1 = Qs[mt * 8 + nt * 2 + 1][tid];
                    float2 q0 = __half22float2(*(__half2*)&u0);
                    float2 q1 = __half22float2(*(__half2*)&u1);
                    part[mt][0] += q0.x * acc[mt][nt][0] + q0.y * acc[mt][nt][1];
                    part[mt][1] += q1.x * acc[mt][nt][2] + q1.y * acc[mt][nt][3];
                }
#pragma unroll
            for (int mt = 0; mt < 2; mt++)
#pragma unroll
                for (int rr = 0; rr < 2; rr++) {
                    float vv = part[mt][rr];
                    vv += __shfl_xor_sync(0xffffffffu, vv, 1);
                    vv += __shfl_xor_sync(0xffffffffu, vv, 2);
                    part[mt][rr] = vv;
                }
            if ((lane & 3) == 0) {
                int rb = wm * 32 + (lane >> 2);
                int h = z * 4 + wn;
#pragma unroll
                for (int mt = 0; mt < 2; mt++)
#pragma unroll
                    for (int rr = 0; rr < 2; rr++) {
                        int r = rb + mt * 16 + rr * 8;
                        int t = toks[r];
                        if (t >= 0) {
                            g_scores[(size_t)h * TOK + t] = part[mt][rr];
                        }
                    }
            }
        } else {
#pragma unroll
            for (int mt = 0; mt < 2; mt++) {
                int rl = wm * 32 + mt * 16 + (lane >> 2);
                int t0 = toks[rl], t1 = toks[rl + 8];
#pragma unroll
                for (int nt = 0; nt < 4; nt++) {
                    int col = z * 128 + wn * 32 + nt * 8 + (lane & 3) * 2;
                    if (t0 >= 0) {
                        *(__half2*)(g_V + (size_t)t0 * D_ + col) = __floats2half2_rn(acc[mt][nt][0], acc[mt][nt][1]);
                    }
                    if (t1 >= 0) {
                        *(__half2*)(g_V + (size_t)t1 * D_ + col) = __floats2half2_rn(acc[mt][nt][2], acc[mt][nt][3]);
                    }
                }
            }
        }
    }
}

// ---------------- attention per batch ----------------
__global__ void __launch_bounds__(256) k_attn(const float* rel_pri, const int* et, const int* ut,
                                              const int* mask, float* dout) {
    int b = blockIdx.x, tid = threadIdx.x, lane = tid & 31, w = tid >> 5;
    __shared__ float attn_s[NH][32];

    int u = ut[b];
    int tok = b * 32 + lane;
    float s = g_scores[(size_t)w * TOK + tok];
    float pri = rel_pri[u * NT + et[tok]];
    s = s * pri * 0.17677669529663689f;   // 1/sqrt(32)
    if (mask[tok] != 0) s = -1e10f;

    float mx = s;
#pragma unroll
    for (int o = 16; o; o >>= 1) mx = fmaxf(mx, __shfl_xor_sync(0xffffffffu, mx, o));
    float ex = expf(s - mx), sm = ex;
#pragma unroll
    for (int o = 16; o; o >>= 1) sm += __shfl_xor_sync(0xffffffffu, sm, o);
    float a = ex / sm;
    attn_s[w][lane] = a;
    dout[(size_t)B_ * D_ + ((size_t)w * B_ + b) * 32 + lane] = a;   // attn_flat
    __syncthreads();

    const __half* Vg = g_V + (size_t)b * 32 * D_;
    float o2 = 0.f;
#pragma unroll
    for (int nn = 0; nn < 32; nn++)
        o2 += attn_s[w][nn] * __half2float(Vg[nn * D_ + w * 32 + lane]);
    g_out[(size_t)b * D_ + tid] = o2;
}

// ---------------- grouped FC projection (by utype) + fused LayerNorm ----------------
// grid (128, NT); CTA = 32 batches x 256 cols. LN done in-block (proj row fully resident).
__global__ void __launch_bounds__(256) k_proj(const float* fc_w, const float* fc_b,
                                              const float* gamma, const float* beta, float* dout) {
    int u = blockIdx.y;
    int cnt = g_hist_u[u];
    int r0 = blockIdx.x * 32;
    if (r0 >= cnt) return;

    __shared__ float outs[32][257];
    __shared__ int bidx[32];
    __shared__ float gs[256], bs[256];
    int tid = threadIdx.x;
    if (tid < 32) {
        int base = 0;
        for (int j = 0; j < NT; j++) { if (j < u) base += g_hist_u[j]; }
        int r = r0 + tid;
        bidx[tid] = (r < cnt) ? g_perm_u[base + r] : -1;
    }
    gs[tid] = gamma[tid];
    bs[tid] = beta[tid];
    __syncthreads();
    for (int i = tid; i < 32 * 256; i += 256) {
        int row = i >> 8, c = i & 255;
        int bb = bidx[row];
        outs[row][c] = (bb >= 0) ? g_out[(size_t)bb * D_ + c] : 0.f;
    }
    __syncthreads();

    int tj = tid & 63, tr = tid >> 6;
    int j0 = tj * 4, bb0 = tr * 8;
    float acc[8][4];
#pragma unroll
    for (int r = 0; r < 8; r++) {
        acc[r][0] = fc_b[u * D_ + j0 + 0];
        acc[r][1] = fc_b[u * D_ + j0 + 1];
        acc[r][2] = fc_b[u * D_ + j0 + 2];
        acc[r][3] = fc_b[u * D_ + j0 + 3];
    }
    const float4* fw = (const float4*)(fc_w + (size_t)u * WSZ + j0);
    for (int i = 0; i < 256; i++) {
        float4 f = fw[(size_t)i * 64];
#pragma unroll
        for (int r = 0; r < 8; r++) {
            float ov = outs[bb0 + r][i];
            acc[r][0] = fmaf(ov, f.x, acc[r][0]);
            acc[r][1] = fmaf(ov, f.y, acc[r][1]);
            acc[r][2] = fmaf(ov, f.z, acc[r][2]);
            acc[r][3] = fmaf(ov, f.w, acc[r][3]);
        }
    }
    __syncthreads();   // everyone done reading outs
    // park projected rows back into outs
#pragma unroll
    for (int r = 0; r < 8; r++) {
        outs[bb0 + r][j0 + 0] = acc[r][0];
        outs[bb0 + r][j0 + 1] = acc[r][1];
        outs[bb0 + r][j0 + 2] = acc[r][2];
        outs[bb0 + r][j0 + 3] = acc[r][3];
    }
    __syncthreads();

    // fused LayerNorm: 8 threads per row, stride-8 column access
    int row = tid >> 3, seg = tid & 7;
    float s1 = 0.f, s2 = 0.f;
#pragma unroll
    for (int i = 0; i < 32; i++) {
        float x = outs[row][seg + i * 8];
        s1 += x;
        s2 += x * x;
    }
#pragma unroll
    for (int o = 1; o < 8; o <<= 1) {
        s1 += __shfl_xor_sync(0xffffffffu, s1, o);
        s2 += __shfl_xor_sync(0xffffffffu, s2, o);
    }
    float mu = s1 * (1.f / 256.f);
    float var = s2 * (1.f / 256.f) - mu * mu;
    float rs = rsqrtf(var + 1e-5f);
    int bb = bidx[row];
    if (bb >= 0) {
#pragma unroll
        for (int i = 0; i < 32; i++) {
            int c = seg + i * 8;
            dout[(size_t)bb * D_ + c] = (outs[row][c] - mu) * rs * gs[c] + bs[c];
        }
    }
}

// ---------------- launch ----------------
extern "C" void kernel_launch(void* const* d_in, const int* in_sizes, int n_in,
                              void* d_out, int out_size) {
    const float* q        = (const float*)d_in[0];
    const float* k        = (const float*)d_in[1];
    const float* v        = (const float*)d_in[2];
    const float* Wq       = (const float*)d_in[3];
    const float* Wk       = (const float*)d_in[4];
    const float* Wv       = (const float*)d_in[5];
    const float* rel_pri  = (const float*)d_in[6];
    const float* fc_w     = (const float*)d_in[7];
    const float* fc_b     = (const float*)d_in[8];
    const float* gamma    = (const float*)d_in[9];
    const float* beta     = (const float*)d_in[10];
    const int*   et       = (const int*)d_in[11];
    const int*   ut       = (const int*)d_in[12];
    const int*   mask     = (const int*)d_in[13];
    float* out = (float*)d_out;

    k_wt<<<dim3(8, 8, 12), dim3(32, 8)>>>(Wq, Wk, Wv);
    k_hist2<<<512, 256>>>(et, ut);
    k_assign2<<<512, 256>>>(et, ut);
    k_fused<<<dim3(2, NT, 2048), 256>>>(q, k, v);
    k_attn<<<B_, 256>>>(rel_pri, et, ut, mask, out);
    k_proj<<<dim3(128, NT), 256>>>(fc_w, fc_b, gamma, beta, out);
}